// round 1
// baseline (speedup 1.0000x reference)
#include <cuda_runtime.h>
#include <cstdint>

// PaddedNeighModule: pair_first is repeat(arange(n_atoms), 64) -> segments are
// contiguous. Per atom: stable-sort its 64 (second, coord) entries by second,
// write jlist_pad (as float) and rijlist_pad.
//
// One warp per atom. Keys: (second << 6) | local_idx  (unique => bitonic sort
// gives the stable order). Coords staged in shared, outputs written coalesced.

#define ATOMS_PER_BLOCK 8
#define THREADS (ATOMS_PER_BLOCK * 32)

__global__ __launch_bounds__(THREADS) void padded_neigh_kernel(
    const int* __restrict__ pair_second,
    const float* __restrict__ pair_coord,
    float* __restrict__ jlist_out,   // [n_atoms * 64]
    float* __restrict__ rij_out,     // [n_atoms * 64 * 3]
    int n_atoms)
{
    __shared__ float         shc[ATOMS_PER_BLOCK][192];  // staged coords per warp
    __shared__ unsigned char shs[ATOMS_PER_BLOCK][64];   // sorted->source index map

    const int warp = threadIdx.x >> 5;
    const int lane = threadIdx.x & 31;
    const int atom = blockIdx.x * ATOMS_PER_BLOCK + warp;
    if (atom >= n_atoms) return;

    const int base = atom * 64;

    // ---- load keys (coalesced) ----
    unsigned s0 = (unsigned)pair_second[base + lane];
    unsigned s1 = (unsigned)pair_second[base + 32 + lane];
    // element ids: i0 = lane (reg bit 0), i1 = 32 | lane (reg bit 1)
    unsigned v0 = (s0 << 6) | (unsigned)lane;
    unsigned v1 = (s1 << 6) | (unsigned)(32 + lane);

    // ---- stage coords into shared (coalesced) ----
    const float* cbase = pair_coord + (size_t)base * 3;
    float* shw = shc[warp];
#pragma unroll
    for (int t = 0; t < 6; t++)
        shw[lane + 32 * t] = cbase[lane + 32 * t];

    // ---- bitonic sort: 64 elems, element id i = (reg<<5) | lane ----
#pragma unroll
    for (int k = 2; k <= 32; k <<= 1) {
#pragma unroll
        for (int j = k >> 1; j >= 1; j >>= 1) {
            const bool up0 = ((lane & k) == 0);                 // i0 & k
            const bool up1 = (((lane | 32) & k) == 0);          // i1 & k (k==32 -> false)
            const bool low = ((lane & j) == 0);                 // same for both regs (j<32)
            unsigned p0 = __shfl_xor_sync(0xffffffffu, v0, j);
            unsigned p1 = __shfl_xor_sync(0xffffffffu, v1, j);
            v0 = (low == up0) ? min(v0, p0) : max(v0, p0);
            v1 = (low == up1) ? min(v1, p1) : max(v1, p1);
        }
    }
    // k = 64 merge: j = 32 is the within-thread exchange (ascending everywhere)
    {
        unsigned t = min(v0, v1);
        v1 = max(v0, v1);
        v0 = t;
    }
#pragma unroll
    for (int j = 16; j >= 1; j >>= 1) {
        const bool low = ((lane & j) == 0);
        unsigned p0 = __shfl_xor_sync(0xffffffffu, v0, j);
        unsigned p1 = __shfl_xor_sync(0xffffffffu, v1, j);
        v0 = low ? min(v0, p0) : max(v0, p0);
        v1 = low ? min(v1, p1) : max(v1, p1);
    }

    // ---- emit ----
    const unsigned sec0 = v0 >> 6, src0 = v0 & 63u;
    const unsigned sec1 = v1 >> 6, src1 = v1 & 63u;

    jlist_out[base + lane]      = (float)sec0;   // rank i0 = lane
    jlist_out[base + 32 + lane] = (float)sec1;   // rank i1 = 32+lane

    shs[warp][lane]      = (unsigned char)src0;
    shs[warp][32 + lane] = (unsigned char)src1;
    __syncwarp();

    // coalesced rij writes: flat f = e*3 + c for this atom; src permutes e
    float* rbase = rij_out + (size_t)base * 3;
#pragma unroll
    for (int t = 0; t < 6; t++) {
        const int idx = lane + 32 * t;      // 0..191
        const int e   = idx / 3;
        const int c   = idx - e * 3;
        const int s   = (int)shs[warp][e];
        rbase[idx] = shw[s * 3 + c];
    }
}

extern "C" void kernel_launch(void* const* d_in, const int* in_sizes, int n_in,
                              void* d_out, int out_size)
{
    // inputs: [0] pair_first (unused: known repeat pattern), [1] pair_second,
    //         [2] pair_coord, [3] atom_array (unused), [4] n_neigh_max (=64)
    const int*   pair_second = (const int*)d_in[1];
    const float* pair_coord  = (const float*)d_in[2];
    const int    n_atoms     = in_sizes[3];

    float* jlist = (float*)d_out;                       // n_atoms*64
    float* rij   = jlist + (size_t)n_atoms * 64;        // n_atoms*64*3

    const int blocks = (n_atoms + ATOMS_PER_BLOCK - 1) / ATOMS_PER_BLOCK;
    padded_neigh_kernel<<<blocks, THREADS>>>(pair_second, pair_coord, jlist, rij, n_atoms);
}

// round 2
// speedup vs baseline: 1.0346x; 1.0346x over previous
#include <cuda_runtime.h>
#include <cstdint>

// PaddedNeighModule: pair_first is repeat(arange(n_atoms), 64) -> segments are
// contiguous, each atom owns exactly 64 pairs. Per atom: stable-sort the 64
// (second, coord) entries by second; emit jlist (as float) + permuted coords.
//
// One warp per atom, 2 elements/thread with id = 2*lane + reg. Keys are
// (second << 6) | id  (unique => bitonic == stable sort). Coords staged in
// shared via float4, outputs written via float4/float2 (all coalesced).

#define ATOMS_PER_BLOCK 8
#define THREADS (ATOMS_PER_BLOCK * 32)

__global__ __launch_bounds__(THREADS) void padded_neigh_kernel(
    const int*   __restrict__ pair_second,
    const float* __restrict__ pair_coord,
    float*       __restrict__ jlist_out,   // [n_atoms * 64]
    float*       __restrict__ rij_out,     // [n_atoms * 64 * 3]
    int n_atoms)
{
    __shared__ __align__(16) float shc[ATOMS_PER_BLOCK][192]; // coords (768B/warp)
    __shared__ unsigned char       shs[ATOMS_PER_BLOCK][64];  // rank -> source idx

    const int warp = threadIdx.x >> 5;
    const int lane = threadIdx.x & 31;
    const int atom = blockIdx.x * ATOMS_PER_BLOCK + warp;
    if (atom >= n_atoms) return;

    const int base = atom * 64;

    // ---- keys: one LDG.64, elements 2*lane and 2*lane+1 ----
    const int2 s2 = ((const int2*)(pair_second + base))[lane];
    unsigned v0 = ((unsigned)s2.x << 6) | (unsigned)(2 * lane);
    unsigned v1 = ((unsigned)s2.y << 6) | (unsigned)(2 * lane + 1);

    // ---- stage coords into shared: 48 float4 per warp ----
    const float* cbase = pair_coord + (size_t)base * 3;
    float* shw = shc[warp];
    {
        const float4* c4 = (const float4*)cbase;
        float4*       s4 = (float4*)shw;
        s4[lane] = c4[lane];
        if (lane < 16) s4[32 + lane] = c4[32 + lane];
    }

    // ---- bitonic sort, 64 elements, id = 2*lane + reg ----
    // j>=2 stages: partner via shfl_xor(j/2), same reg; dir/low shared by both regs.
    // j==1 stages: in-thread compare-exchange of (v0, v1).
#pragma unroll
    for (int k = 2; k <= 64; k <<= 1) {
        const int kh = k >> 1;
        const bool dir = ((lane & kh) == 0);   // (id & k) == 0 for both regs
#pragma unroll
        for (int j = kh; j >= 2; j >>= 1) {
            const int  sh  = j >> 1;
            const bool low = ((lane & sh) == 0);   // (id & j) == 0
            unsigned p0 = __shfl_xor_sync(0xffffffffu, v0, sh);
            unsigned p1 = __shfl_xor_sync(0xffffffffu, v1, sh);
            const bool keepmin = (low == dir);
            v0 = keepmin ? min(v0, p0) : max(v0, p0);
            v1 = keepmin ? min(v1, p1) : max(v1, p1);
        }
        // j == 1: in-thread
        {
            unsigned lo = min(v0, v1), hi = max(v0, v1);
            v0 = dir ? lo : hi;
            v1 = dir ? hi : lo;
        }
    }

    // thread now holds ranks 2*lane (v0) and 2*lane+1 (v1)

    // ---- jlist: adjacent ranks -> one STG.64 ----
    {
        float2 jf = make_float2((float)(v0 >> 6), (float)(v1 >> 6));
        ((float2*)(jlist_out + base))[lane] = jf;
    }

    // ---- publish rank->source map (one STS.16) ----
    {
        uchar2 sm = make_uchar2((unsigned char)(v0 & 63u), (unsigned char)(v1 & 63u));
        ((uchar2*)shs[warp])[lane] = sm;
    }
    __syncwarp();

    // ---- permuted coord write: compose float4s, 48 STG.128 per warp ----
    float4* r4 = (float4*)(rij_out + (size_t)base * 3);
    const unsigned char* sm = shs[warp];
#pragma unroll
    for (int q = 0; q < 2; q++) {
        const int idx = lane + 32 * q;            // float4 index 0..47
        if (q == 1 && lane >= 16) break;
        const int f = 4 * idx;                    // first flat float, 0..188
        float4 o;
        {
            int e = (f + 0) / 3, c = (f + 0) - e * 3;
            o.x = shw[(int)sm[e] * 3 + c];
        }
        {
            int e = (f + 1) / 3, c = (f + 1) - e * 3;
            o.y = shw[(int)sm[e] * 3 + c];
        }
        {
            int e = (f + 2) / 3, c = (f + 2) - e * 3;
            o.z = shw[(int)sm[e] * 3 + c];
        }
        {
            int e = (f + 3) / 3, c = (f + 3) - e * 3;
            o.w = shw[(int)sm[e] * 3 + c];
        }
        r4[idx] = o;
    }
}

extern "C" void kernel_launch(void* const* d_in, const int* in_sizes, int n_in,
                              void* d_out, int out_size)
{
    // inputs: [0] pair_first (unused), [1] pair_second, [2] pair_coord,
    //         [3] atom_array (unused, gives n_atoms), [4] n_neigh_max (=64)
    const int*   pair_second = (const int*)d_in[1];
    const float* pair_coord  = (const float*)d_in[2];
    const int    n_atoms     = in_sizes[3];

    float* jlist = (float*)d_out;                    // n_atoms*64
    float* rij   = jlist + (size_t)n_atoms * 64;     // n_atoms*64*3

    const int blocks = (n_atoms + ATOMS_PER_BLOCK - 1) / ATOMS_PER_BLOCK;
    padded_neigh_kernel<<<blocks, THREADS>>>(pair_second, pair_coord, jlist, rij, n_atoms);
}

// round 3
// speedup vs baseline: 1.1053x; 1.0683x over previous
#include <cuda_runtime.h>
#include <cstdint>

// PaddedNeighModule: pair_first = repeat(arange(n_atoms), 64) -> contiguous
// 64-pair segments. Per atom: stable-sort by pair_second, emit jlist (float)
// and permuted coords.
//
// One warp per atom, 2 elements/thread (ids 2*lane, 2*lane+1). Bitonic sort on
// keys (second<<6)|id (unique => stable order). Epilogue uses the INVERSE
// permutation: scatter rank by src, each thread pushes its own 6 coords into a
// shared output buffer at rank*3, then coalesced float4 drain to global.

#define ATOMS_PER_BLOCK 8
#define THREADS (ATOMS_PER_BLOCK * 32)

__global__ __launch_bounds__(THREADS) void padded_neigh_kernel(
    const int*   __restrict__ pair_second,
    const float* __restrict__ pair_coord,
    float*       __restrict__ jlist_out,   // [n_atoms * 64]
    float*       __restrict__ rij_out,     // [n_atoms * 64 * 3]
    int n_atoms)
{
    __shared__ __align__(16) float sho[ATOMS_PER_BLOCK][192]; // output-ordered coords
    __shared__ unsigned char       shs[ATOMS_PER_BLOCK][64];  // src -> rank (inverse map)

    const int warp = threadIdx.x >> 5;
    const int lane = threadIdx.x & 31;
    const int atom = blockIdx.x * ATOMS_PER_BLOCK + warp;
    if (atom >= n_atoms) return;

    const int base = atom * 64;

    // ---- keys: one LDG.64, thread owns elements 2*lane and 2*lane+1 ----
    const int2 s2 = ((const int2*)(pair_second + base))[lane];
    unsigned v0 = ((unsigned)s2.x << 6) | (unsigned)(2 * lane);
    unsigned v1 = ((unsigned)s2.y << 6) | (unsigned)(2 * lane + 1);

    // ---- own coords: elements 2*lane -> floats [6*lane..6*lane+2],
    //      2*lane+1 -> [6*lane+3..6*lane+5]; three LDG.64 ----
    const float2* c2 = (const float2*)(pair_coord + (size_t)base * 3);
    const float2 ca = c2[3 * lane + 0];
    const float2 cb = c2[3 * lane + 1];
    const float2 cc = c2[3 * lane + 2];

    // ---- bitonic sort, 64 elements, id = 2*lane + reg ----
#pragma unroll
    for (int k = 2; k <= 64; k <<= 1) {
        const int kh = k >> 1;
        const bool dir = ((lane & kh) == 0);   // (id & k) == 0, same for both regs
#pragma unroll
        for (int j = kh; j >= 2; j >>= 1) {
            const int  sh  = j >> 1;
            const bool low = ((lane & sh) == 0);   // (id & j) == 0
            unsigned p0 = __shfl_xor_sync(0xffffffffu, v0, sh);
            unsigned p1 = __shfl_xor_sync(0xffffffffu, v1, sh);
            const bool keepmin = (low == dir);
            v0 = keepmin ? min(v0, p0) : max(v0, p0);
            v1 = keepmin ? min(v1, p1) : max(v1, p1);
        }
        // j == 1: in-thread compare-exchange
        {
            unsigned lo = min(v0, v1), hi = max(v0, v1);
            v0 = dir ? lo : hi;
            v1 = dir ? hi : lo;
        }
    }
    // thread now holds rank 2*lane (v0) and rank 2*lane+1 (v1)

    // ---- jlist: adjacent ranks -> one STG.64 ----
    ((float2*)(jlist_out + base))[lane] =
        make_float2((float)(v0 >> 6), (float)(v1 >> 6));

    // ---- inverse permutation: shs[src] = rank ----
    unsigned char* sm = shs[warp];
    sm[v0 & 63u] = (unsigned char)(2 * lane);
    sm[v1 & 63u] = (unsigned char)(2 * lane + 1);
    __syncwarp();

    // ---- ranks of this thread's own elements ----
    const uchar2 rr = ((const uchar2*)sm)[lane];   // rr.x = rank of 2*lane, rr.y = rank of 2*lane+1
    const int p0 = (int)rr.x * 3;
    const int p1 = (int)rr.y * 3;

    // ---- scatter own coords into output-ordered shared buffer ----
    float* o = sho[warp];
    o[p0 + 0] = ca.x;  o[p0 + 1] = ca.y;  o[p0 + 2] = cb.x;
    o[p1 + 0] = cb.y;  o[p1 + 1] = cc.x;  o[p1 + 2] = cc.y;
    __syncwarp();

    // ---- coalesced drain: 48 float4 per warp ----
    float4*       r4 = (float4*)(rij_out + (size_t)base * 3);
    const float4* s4 = (const float4*)o;
    r4[lane] = s4[lane];
    if (lane < 16) r4[32 + lane] = s4[32 + lane];
}

extern "C" void kernel_launch(void* const* d_in, const int* in_sizes, int n_in,
                              void* d_out, int out_size)
{
    // inputs: [0] pair_first (unused), [1] pair_second, [2] pair_coord,
    //         [3] atom_array (unused, gives n_atoms), [4] n_neigh_max (=64)
    const int*   pair_second = (const int*)d_in[1];
    const float* pair_coord  = (const float*)d_in[2];
    const int    n_atoms     = in_sizes[3];

    float* jlist = (float*)d_out;                    // n_atoms*64
    float* rij   = jlist + (size_t)n_atoms * 64;     // n_atoms*64*3

    const int blocks = (n_atoms + ATOMS_PER_BLOCK - 1) / ATOMS_PER_BLOCK;
    padded_neigh_kernel<<<blocks, THREADS>>>(pair_second, pair_coord, jlist, rij, n_atoms);
}

// round 5
// speedup vs baseline: 1.1748x; 1.0629x over previous
#include <cuda_runtime.h>
#include <cstdint>

// PaddedNeighModule: pair_first = repeat(arange(n_atoms), 64) -> contiguous
// 64-pair segments. Per atom: stable-sort by pair_second, emit jlist (float)
// and permuted coords.
//
// TWO atoms per warp: lanes 0-15 = atom A, lanes 16-31 = atom B. Each thread
// holds 4 elements (ids 4*ll+reg). Bitonic sort on keys (second<<6)|id
// (unique => stable). Stages j<=2 are in-thread; only 10 of 21 stages shuffle.
// Epilogue: inverse permutation scatter into shared, coalesced float4 drain.

#define WARPS_PER_BLOCK 8
#define ATOMS_PER_BLOCK (2 * WARPS_PER_BLOCK)
#define THREADS (WARPS_PER_BLOCK * 32)

#define CMPX(a, b, asc)                                   \
    {                                                     \
        unsigned _lo = min(a, b), _hi = max(a, b);        \
        a = (asc) ? _lo : _hi;                            \
        b = (asc) ? _hi : _lo;                            \
    }

__global__ __launch_bounds__(THREADS) void padded_neigh_kernel(
    const int*   __restrict__ pair_second,
    const float* __restrict__ pair_coord,
    float*       __restrict__ jlist_out,   // [n_atoms * 64]
    float*       __restrict__ rij_out,     // [n_atoms * 64 * 3]
    int n_atoms)
{
    // per warp: 2 atoms -> 384 output floats, 128 map bytes
    __shared__ __align__(16) float sho[WARPS_PER_BLOCK][384];
    __shared__ unsigned char       shs[WARPS_PER_BLOCK][128];

    const int warp = threadIdx.x >> 5;
    const int lane = threadIdx.x & 31;
    const int ll   = lane & 15;      // lane within atom group
    const int g    = lane >> 4;      // 0 = atom A, 1 = atom B

    const int atom  = blockIdx.x * ATOMS_PER_BLOCK + 2 * warp + g;
    const bool valid = (atom < n_atoms);
    const int satom = valid ? atom : (n_atoms - 1);   // safe load address
    const int base  = satom * 64;

    // ---- keys: one LDG.128, elements 4*ll .. 4*ll+3 ----
    const int4 k4 = ((const int4*)(pair_second + base))[ll];
    unsigned v0 = ((unsigned)k4.x << 6) | (unsigned)(4 * ll + 0);
    unsigned v1 = ((unsigned)k4.y << 6) | (unsigned)(4 * ll + 1);
    unsigned v2 = ((unsigned)k4.z << 6) | (unsigned)(4 * ll + 2);
    unsigned v3 = ((unsigned)k4.w << 6) | (unsigned)(4 * ll + 3);

    // ---- own coords: floats [12*ll, 12*ll+12) = 3 aligned float4 ----
    const float4* c4 = (const float4*)(pair_coord + (size_t)base * 3);
    const float4 ca = c4[3 * ll + 0];   // e0: ca.x ca.y ca.z | e1 starts ca.w
    const float4 cb = c4[3 * ll + 1];   // e1: cb.x cb.y | e2: cb.z cb.w ...
    const float4 cc = c4[3 * ll + 2];   // e2: cc.x | e3: cc.y cc.z cc.w

    // ---- bitonic sort, 64 elements per atom group, id = 4*ll + reg ----
    // k = 2: pair (e0,e1) ascending, (e2,e3) descending
    CMPX(v0, v1, true);
    CMPX(v2, v3, false);
    // k = 4: dir uniform per thread
    {
        const bool dir = ((ll & 1) == 0);
        CMPX(v0, v2, dir); CMPX(v1, v3, dir);   // j = 2
        CMPX(v0, v1, dir); CMPX(v2, v3, dir);   // j = 1
    }
    // k = 8, 16, 32, 64
#pragma unroll
    for (int k = 8; k <= 64; k <<= 1) {
        const bool dir = ((ll & (k >> 2)) == 0);   // (id & k) == 0
#pragma unroll
        for (int j = k >> 1; j >= 4; j >>= 1) {
            const int  d   = j >> 2;                  // shfl distance (1,2,4,8)
            const bool low = ((ll & d) == 0);         // (id & j) == 0
            const bool keepmin = (low == dir);
            unsigned p;
            p = __shfl_xor_sync(0xffffffffu, v0, d); v0 = keepmin ? min(v0, p) : max(v0, p);
            p = __shfl_xor_sync(0xffffffffu, v1, d); v1 = keepmin ? min(v1, p) : max(v1, p);
            p = __shfl_xor_sync(0xffffffffu, v2, d); v2 = keepmin ? min(v2, p) : max(v2, p);
            p = __shfl_xor_sync(0xffffffffu, v3, d); v3 = keepmin ? min(v3, p) : max(v3, p);
        }
        CMPX(v0, v2, dir); CMPX(v1, v3, dir);   // j = 2
        CMPX(v0, v1, dir); CMPX(v2, v3, dir);   // j = 1
    }
    // thread now holds ranks 4*ll .. 4*ll+3 (sorted keys)

    // ---- jlist: 4 consecutive ranks -> one STG.128 ----
    if (valid) {
        ((float4*)(jlist_out + base))[ll] =
            make_float4((float)(v0 >> 6), (float)(v1 >> 6),
                        (float)(v2 >> 6), (float)(v3 >> 6));
    }

    // ---- inverse permutation: sm[src] = rank ----
    unsigned char* sm = shs[warp] + g * 64;
    sm[v0 & 63u] = (unsigned char)(4 * ll + 0);
    sm[v1 & 63u] = (unsigned char)(4 * ll + 1);
    sm[v2 & 63u] = (unsigned char)(4 * ll + 2);
    sm[v3 & 63u] = (unsigned char)(4 * ll + 3);
    __syncwarp();

    // ranks of this thread's own elements e0..e3 (one LDS.32; groups hit
    // disjoint bank halves)
    const uchar4 rr = ((const uchar4*)sm)[ll];

    // ---- scatter own coords into output-ordered shared buffer ----
    float* o = sho[warp] + g * 192;
    {
        const int p0 = (int)rr.x * 3, p1 = (int)rr.y * 3;
        const int p2 = (int)rr.z * 3, p3 = (int)rr.w * 3;
        o[p0 + 0] = ca.x;  o[p0 + 1] = ca.y;  o[p0 + 2] = ca.z;
        o[p1 + 0] = ca.w;  o[p1 + 1] = cb.x;  o[p1 + 2] = cb.y;
        o[p2 + 0] = cb.z;  o[p2 + 1] = cb.w;  o[p2 + 2] = cc.x;
        o[p3 + 0] = cc.y;  o[p3 + 1] = cc.z;  o[p3 + 2] = cc.w;
    }
    __syncwarp();

    // ---- coalesced drain: 3 float4 per thread (covers both atoms) ----
    if (valid) {
        float4*       r4 = (float4*)(rij_out + (size_t)satom * 192);
        const float4* s4 = (const float4*)o;
        r4[ll]      = s4[ll];
        r4[16 + ll] = s4[16 + ll];
        r4[32 + ll] = s4[32 + ll];
    }
}

extern "C" void kernel_launch(void* const* d_in, const int* in_sizes, int n_in,
                              void* d_out, int out_size)
{
    // inputs: [0] pair_first (unused), [1] pair_second, [2] pair_coord,
    //         [3] atom_array (unused, gives n_atoms), [4] n_neigh_max (=64)
    const int*   pair_second = (const int*)d_in[1];
    const float* pair_coord  = (const float*)d_in[2];
    const int    n_atoms     = in_sizes[3];

    float* jlist = (float*)d_out;                    // n_atoms*64
    float* rij   = jlist + (size_t)n_atoms * 64;     // n_atoms*64*3

    const int blocks = (n_atoms + ATOMS_PER_BLOCK - 1) / ATOMS_PER_BLOCK;
    padded_neigh_kernel<<<blocks, THREADS>>>(pair_second, pair_coord, jlist, rij, n_atoms);
}